// round 3
// baseline (speedup 1.0000x reference)
#include <cuda_runtime.h>
#include <cstdint>

// BsplineEncoding: x[N=1e6, D=3] -> out[N, D*(1+K)] with K=64, cubic (DEG=3).
// Layout per point: for each dim d: [x_d, feat_d[0..63]] concatenated -> 195 floats.
// Only 4 of 64 feature bins per dim are nonzero, but ALL 195 floats must be
// written (harness poisons d_out). => pure HBM-write-bound: 780 MB out.
//
// Strategy: flat float4 iteration over the 195M-float output. Each thread
// computes 4 consecutive elements from scratch and issues one STG.128.
// 195e6 % 4 == 0 and d_out is 256B-aligned, so all stores are clean 16B.

static constexpr float MIN_VAL  = -1.0f;
static constexpr float SCALE    = 30.5f;            // (K - DEG) / (MAX - MIN) = 61/2
static constexpr float CLAMP_HI = 61.0f - 1e-6f;    // K - DEG - EPS
static constexpr unsigned OUT_PER_POINT = 195u;     // 3 * (1 + 64)
static constexpr unsigned OUT_PER_DIM   = 65u;      // 1 + 64

__global__ __launch_bounds__(256)
void bspline_enc_kernel(const float* __restrict__ xin,
                        float* __restrict__ out,
                        int n_vec4)
{
    int i = blockIdx.x * blockDim.x + threadIdx.x;
    if (i >= n_vec4) return;

    unsigned base = (unsigned)i * 4u;
    float vals[4];

#pragma unroll
    for (int c = 0; c < 4; ++c) {
        unsigned e   = base + (unsigned)c;
        unsigned n   = e / OUT_PER_POINT;            // point index (mulhi const)
        unsigned rem = e - n * OUT_PER_POINT;
        unsigned d   = rem / OUT_PER_DIM;            // dim 0..2
        unsigned r   = rem - d * OUT_PER_DIM;        // 0 = raw x, 1..64 = bin r-1

        float xv = __ldg(xin + n * 3u + d);          // hot in L1: 65 elems share it

        float val;
        if (r == 0u) {
            val = xv;
        } else {
            float xs = fminf(fmaxf((xv - MIN_VAL) * SCALE, 0.0f), CLAMP_HI);
            float fi = floorf(xs);
            int   j  = (int)r - 1 - (int)fi;         // which of the 4 basis fns
            float u  = xs - fi;
            float u2 = u * u;
            float u3 = u2 * u;
            float om = 1.0f - u;
            float c0 = om * om * om * (1.0f / 6.0f);
            float c1 = (3.0f * u3 - 6.0f * u2 + 4.0f) * (1.0f / 6.0f);
            float c2 = (-3.0f * u3 + 3.0f * u2 + 3.0f * u + 1.0f) * (1.0f / 6.0f);
            float c3 = u3 * (1.0f / 6.0f);
            // branchless select -> FSEL chain, no divergence
            val = (j == 0) ? c0
                : (j == 1) ? c1
                : (j == 2) ? c2
                : (j == 3) ? c3
                : 0.0f;
        }
        vals[c] = val;
    }

    float4 v = make_float4(vals[0], vals[1], vals[2], vals[3]);
    reinterpret_cast<float4*>(out)[i] = v;
}

extern "C" void kernel_launch(void* const* d_in, const int* in_sizes, int n_in,
                              void* d_out, int out_size)
{
    const float* x = (const float*)d_in[0];
    float* out = (float*)d_out;

    // out_size = N * 195 floats; guaranteed divisible by 4 for N = 1e6.
    int n_vec4 = out_size / 4;

    const int threads = 256;
    int blocks = (n_vec4 + threads - 1) / threads;
    bspline_enc_kernel<<<blocks, threads>>>(x, out, n_vec4);
}

// round 4
// speedup vs baseline: 3.7907x; 3.7907x over previous
#include <cuda_runtime.h>
#include <cstdint>

// BsplineEncoding: x[1e6, 3] -> out[1e6, 195] (per dim: [x_d, 64 feature bins],
// only 4 bins nonzero). All 195M floats must be written (poisoned output).
//
// R1 lesson: computing the spline + index decomposition per OUTPUT element is
// issue-bound (445us, DRAM 20.8%). Fix: evaluate the spline once per
// (point,dim) (3M evals instead of 195M selects), scatter into a zeroed
// shared tile, then stream the tile out with coalesced float4 stores.
//
// Tiling: 32 points/block -> 6240 floats (24.96 KB) shared, 1e6/32 = 31250
// blocks exactly (no tail). Tile byte offset 24960*blk is 16B-aligned.

static constexpr float SCALE    = 30.5f;            // (K-DEG)/(MAX-MIN) = 61/2
static constexpr float CLAMP_HI = 61.0f - 1e-6f;    // K - DEG - EPS
static constexpr int   PTS_PER_BLK = 32;
static constexpr int   TILE_FLOATS = PTS_PER_BLK * 195;   // 6240
static constexpr int   TILE_VEC4   = TILE_FLOATS / 4;     // 1560
static constexpr int   THREADS     = 256;

__global__ __launch_bounds__(THREADS)
void bspline_enc_kernel(const float* __restrict__ xin,
                        float* __restrict__ out)
{
    __shared__ float tile[TILE_FLOATS];
    const int tid = threadIdx.x;

    // Phase 1: zero the tile (float4 stores, conflict-free).
    float4 z4 = make_float4(0.f, 0.f, 0.f, 0.f);
    float4* t4 = reinterpret_cast<float4*>(tile);
#pragma unroll
    for (int i = tid; i < TILE_VEC4; i += THREADS)
        t4[i] = z4;
    __syncthreads();

    // Phase 2: 96 workers, one per (point, dim). Input load is perfectly
    // coalesced: global element index = blk*96 + tid.
    if (tid < PTS_PER_BLK * 3) {
        const int p = tid / 3;              // local point
        const int d = tid - p * 3;          // dim
        const float xv = __ldg(xin + (size_t)blockIdx.x * (PTS_PER_BLK * 3) + tid);

        float xs = fminf(fmaxf((xv + 1.0f) * SCALE, 0.0f), CLAMP_HI);
        float fi = floorf(xs);
        int  idx = (int)fi;
        float u  = xs - fi;
        float u2 = u * u;
        float u3 = u2 * u;
        float om = 1.0f - u;
        float c0 = om * om * om * (1.0f / 6.0f);
        float c1 = (3.0f * u3 - 6.0f * u2 + 4.0f) * (1.0f / 6.0f);
        float c2 = (-3.0f * u3 + 3.0f * u2 + 3.0f * u + 1.0f) * (1.0f / 6.0f);
        float c3 = u3 * (1.0f / 6.0f);

        float* dst = tile + p * 195 + d * 65;
        dst[0]       = xv;
        dst[1 + idx] = c0;
        dst[2 + idx] = c1;
        dst[3 + idx] = c2;
        dst[4 + idx] = c3;
    }
    __syncthreads();

    // Phase 3: coalesced float4 stream to global.
    float4* o4 = reinterpret_cast<float4*>(out) + (size_t)blockIdx.x * TILE_VEC4;
#pragma unroll
    for (int i = tid; i < TILE_VEC4; i += THREADS)
        o4[i] = t4[i];
}

extern "C" void kernel_launch(void* const* d_in, const int* in_sizes, int n_in,
                              void* d_out, int out_size)
{
    const float* x = (const float*)d_in[0];
    float* out = (float*)d_out;

    // out_size = 1e6 * 195; points = out_size / 195; blocks = points / 32.
    int n_points = out_size / 195;
    int blocks   = n_points / PTS_PER_BLK;   // 31250, exact for N = 1e6
    bspline_enc_kernel<<<blocks, THREADS>>>(x, out);
}